// round 7
// baseline (speedup 1.0000x reference)
#include <cuda_runtime.h>
#include <cstdint>

// ---------------- problem dims ----------------
#define BATCH 4
#define SEQ   2048
#define DIM   1024
#define BT    (BATCH*SEQ)          // 8192

// ---------------- tile config ----------------
#define BM 128
#define BN 256
#define BK 32
#define NT 256                     // 8 warps, warp tile 64x64
#define SKA 36                     // [row][k] stride (pad 4) for A and NT-B
#define SKB 260                    // [k][n] stride (pad 4) for NN-B (n=256)

// ---------------- scratch (no allocs allowed) ----------------
__device__ float g_Q[BATCH*SEQ*DIM];
__device__ float g_K[BATCH*SEQ*DIM];
__device__ float g_V[BATCH*SEQ*DIM];
__device__ float g_S[(long)BATCH*SEQ*SEQ];

// ---------------- tf32 helpers ----------------
__device__ __forceinline__ uint32_t f2tf(float f) {
    uint32_t u;
    asm("cvt.rna.tf32.f32 %0, %1;" : "=r"(u) : "f"(f));
    return u;
}
__device__ __forceinline__ uint4 f2tf4(float4 v) {
    return make_uint4(f2tf(v.x), f2tf(v.y), f2tf(v.z), f2tf(v.w));
}

__device__ __forceinline__ void mma8(float* c,
                                     uint32_t a0, uint32_t a1, uint32_t a2, uint32_t a3,
                                     uint32_t b0, uint32_t b1)
{
    asm volatile(
        "mma.sync.aligned.m16n8k8.row.col.f32.tf32.tf32.f32 "
        "{%0,%1,%2,%3}, {%4,%5,%6,%7}, {%8,%9}, {%0,%1,%2,%3};"
        : "+f"(c[0]), "+f"(c[1]), "+f"(c[2]), "+f"(c[3])
        : "r"(a0), "r"(a1), "r"(a2), "r"(a3), "r"(b0), "r"(b1));
}

// smem words per buffer
#define A_WORDS (BM * SKA)                 // 4608
#define BNT_WORDS (BN * SKA)               // 9216
#define BNN_WORDS (BK * SKB)               // 8320

// ============================================================
// 128x256x32 TF32 tensor-core GEMM, double-buffered smem,
// LDG reg-prefetch, STS.128 staging.
// A: [M,K] row-major. BNT=true: B [N,K] row-major (C = A*B^T).
//                     BNT=false: B [K,N] row-major (C = A*B).
// 8 warps 2(M) x 4(N), warp tile 64x64 -> 4 m16 x 8 n8 MMAs.
// ============================================================
template<bool BNT>
__device__ __forceinline__ void gemm_tile(const float* __restrict__ A,
                                          const float* __restrict__ B,
                                          float* __restrict__ C,
                                          int N, int K, float alpha)
{
    extern __shared__ uint32_t smem[];
    uint32_t* Asb[2] = { smem, smem + A_WORDS };
    uint32_t* Bsb[2] = { smem + 2*A_WORDS,
                         smem + 2*A_WORDS + (BNT ? BNT_WORDS : BNN_WORDS) };

    const int tid  = threadIdx.x;
    const int lane = tid & 31;
    const int warp = tid >> 5;
    const int wm   = warp >> 2;        // 0..1
    const int wn   = warp & 3;         // 0..3
    const int lr   = lane >> 2;        // 0..7
    const int lc   = lane & 3;         // 0..3
    const int m0   = blockIdx.y * BM;
    const int n0   = blockIdx.x * BN;

    float acc[4][8][4];
#pragma unroll
    for (int i = 0; i < 4; ++i)
#pragma unroll
        for (int j = 0; j < 8; ++j)
#pragma unroll
            for (int e = 0; e < 4; ++e) acc[i][j][e] = 0.f;

    float4 pfA[4], pfB[8];

    // ---- prologue: LDG tile k0=0
    {
        const float* Ab = A + (long)m0 * K;
#pragma unroll
        for (int i = 0; i < 4; ++i) {
            int idx = tid + i * NT;         // 0..1023
            int r   = idx >> 3;             // 0..127
            int c4  = idx & 7;
            pfA[i] = *(const float4*)(Ab + (long)r * K + c4 * 4);
        }
        if (BNT) {
            const float* Bb = B + (long)n0 * K;
#pragma unroll
            for (int i = 0; i < 8; ++i) {
                int idx = tid + i * NT;     // 0..2047
                int r   = idx >> 3;         // 0..255
                int c4  = idx & 7;
                pfB[i] = *(const float4*)(Bb + (long)r * K + c4 * 4);
            }
        } else {
            const float* Bb = B + n0;
#pragma unroll
            for (int i = 0; i < 8; ++i) {
                int idx = tid + i * NT;     // 0..2047
                int kr  = idx >> 6;         // 0..31
                int c4  = idx & 63;         // 0..63
                pfB[i] = *(const float4*)(Bb + (long)kr * N + c4 * 4);
            }
        }
    }

    int buf = 0;
    for (int k0 = 0; k0 < K; k0 += BK) {
        uint32_t* As = Asb[buf];
        uint32_t* Bs = Bsb[buf];

        // ---- STS.128 staged registers (tf32-converted)
#pragma unroll
        for (int i = 0; i < 4; ++i) {
            int idx = tid + i * NT;
            int r   = idx >> 3;
            int c4  = idx & 7;
            *(uint4*)&As[r * SKA + c4 * 4] = f2tf4(pfA[i]);
        }
        if (BNT) {
#pragma unroll
            for (int i = 0; i < 8; ++i) {
                int idx = tid + i * NT;
                int r   = idx >> 3;
                int c4  = idx & 7;
                *(uint4*)&Bs[r * SKA + c4 * 4] = f2tf4(pfB[i]);
            }
        } else {
#pragma unroll
            for (int i = 0; i < 8; ++i) {
                int idx = tid + i * NT;
                int kr  = idx >> 6;
                int c4  = idx & 63;
                *(uint4*)&Bs[kr * SKB + c4 * 4] = f2tf4(pfB[i]);
            }
        }
        __syncthreads();

        // ---- prefetch next slab (overlaps MMAs across warps)
        if (k0 + BK < K) {
            const float* Ab = A + (long)m0 * K + (k0 + BK);
#pragma unroll
            for (int i = 0; i < 4; ++i) {
                int idx = tid + i * NT;
                int r   = idx >> 3;
                int c4  = idx & 7;
                pfA[i] = *(const float4*)(Ab + (long)r * K + c4 * 4);
            }
            if (BNT) {
                const float* Bb = B + (long)n0 * K + (k0 + BK);
#pragma unroll
                for (int i = 0; i < 8; ++i) {
                    int idx = tid + i * NT;
                    int r   = idx >> 3;
                    int c4  = idx & 7;
                    pfB[i] = *(const float4*)(Bb + (long)r * K + c4 * 4);
                }
            } else {
                const float* Bb = B + (long)(k0 + BK) * N + n0;
#pragma unroll
                for (int i = 0; i < 8; ++i) {
                    int idx = tid + i * NT;
                    int kr  = idx >> 6;
                    int c4  = idx & 63;
                    pfB[i] = *(const float4*)(Bb + (long)kr * N + c4 * 4);
                }
            }
        }

        // ---- 4 k8-steps of MMAs (32 MMAs each)
#pragma unroll
        for (int ks = 0; ks < BK; ks += 8) {
            uint32_t af[4][4];
#pragma unroll
            for (int mt = 0; mt < 4; ++mt) {
                int r = wm * 64 + mt * 16 + lr;
                const uint32_t* p = &As[r * SKA + ks + lc];
                af[mt][0] = p[0];
                af[mt][1] = p[8 * SKA];
                af[mt][2] = p[4];
                af[mt][3] = p[8 * SKA + 4];
            }
            uint32_t bf[8][2];
            if (BNT) {
#pragma unroll
                for (int nt = 0; nt < 8; ++nt) {
                    int n = wn * 64 + nt * 8 + lr;
                    const uint32_t* p = &Bs[n * SKA + ks + lc];
                    bf[nt][0] = p[0];
                    bf[nt][1] = p[4];
                }
            } else {
#pragma unroll
                for (int nt = 0; nt < 8; ++nt) {
                    const uint32_t* p = &Bs[(ks + lc) * SKB + wn * 64 + nt * 8 + lr];
                    bf[nt][0] = p[0];
                    bf[nt][1] = p[4 * SKB];
                }
            }
#pragma unroll
            for (int mt = 0; mt < 4; ++mt)
#pragma unroll
                for (int nt = 0; nt < 8; ++nt)
                    mma8(acc[mt][nt],
                         af[mt][0], af[mt][1], af[mt][2], af[mt][3],
                         bf[nt][0], bf[nt][1]);
        }
        buf ^= 1;
    }

    // ---- epilogue
#pragma unroll
    for (int mt = 0; mt < 4; ++mt) {
#pragma unroll
        for (int nt = 0; nt < 8; ++nt) {
            int r = m0 + wm * 64 + mt * 16 + lr;
            int c = n0 + wn * 64 + nt * 8 + 2 * lc;
            float2 v0 = make_float2(acc[mt][nt][0] * alpha, acc[mt][nt][1] * alpha);
            float2 v1 = make_float2(acc[mt][nt][2] * alpha, acc[mt][nt][3] * alpha);
            *(float2*)&C[(long)r * N + c]       = v0;
            *(float2*)&C[(long)(r + 8) * N + c] = v1;
        }
    }
}

// ---- dynamic smem sizes
#define SMEM_NT ((2*A_WORDS + 2*BNT_WORDS) * 4)   // 110,592 B
#define SMEM_NN ((2*A_WORDS + 2*BNN_WORDS) * 4)   // 103,424 B

// ============================================================
// Kernels
// ============================================================

__global__ __launch_bounds__(NT, 1)
void qkv_kernel(const float* __restrict__ x,
                const float* __restrict__ Wq,
                const float* __restrict__ Wk,
                const float* __restrict__ Wv)
{
    const float* W = (blockIdx.z == 0) ? Wq : (blockIdx.z == 1) ? Wk : Wv;
    float*       C = (blockIdx.z == 0) ? g_Q : (blockIdx.z == 1) ? g_K : g_V;
    gemm_tile<true>(x, W, C, DIM, DIM, 1.0f);
}

__global__ __launch_bounds__(NT, 1)
void scores_kernel()
{
    long z = blockIdx.z;
    gemm_tile<true>(g_Q + z * (long)SEQ * DIM,
                    g_K + z * (long)SEQ * DIM,
                    g_S + z * (long)SEQ * SEQ,
                    SEQ, DIM, 0.03125f /* 1/sqrt(1024) */);
}

__global__ __launch_bounds__(NT)
void softmax_kernel()
{
    long row = blockIdx.x;
    float4* p = (float4*)(g_S + row * (long)SEQ);
    const int n4 = SEQ / 4;
    int tid = threadIdx.x;
    __shared__ float red[NT];

    float m = -1e30f;
    for (int i = tid; i < n4; i += NT) {
        float4 v = p[i];
        m = fmaxf(m, fmaxf(fmaxf(v.x, v.y), fmaxf(v.z, v.w)));
    }
    red[tid] = m; __syncthreads();
    for (int s = NT / 2; s > 0; s >>= 1) {
        if (tid < s) red[tid] = fmaxf(red[tid], red[tid + s]);
        __syncthreads();
    }
    m = red[0]; __syncthreads();

    float sum = 0.f;
    for (int i = tid; i < n4; i += NT) {
        float4 v = p[i];
        v.x = __expf(v.x - m); v.y = __expf(v.y - m);
        v.z = __expf(v.z - m); v.w = __expf(v.w - m);
        p[i] = v;
        sum += v.x + v.y + v.z + v.w;
    }
    red[tid] = sum; __syncthreads();
    for (int s = NT / 2; s > 0; s >>= 1) {
        if (tid < s) red[tid] += red[tid + s];
        __syncthreads();
    }
    float inv = 1.f / red[0];

    for (int i = tid; i < n4; i += NT) {
        float4 v = p[i];
        v.x *= inv; v.y *= inv; v.z *= inv; v.w *= inv;
        p[i] = v;
    }
}

__global__ __launch_bounds__(NT, 1)
void out_kernel(float* __restrict__ out)
{
    long z = blockIdx.z;
    gemm_tile<false>(g_S + z * (long)SEQ * SEQ,
                     g_V + z * (long)SEQ * DIM,
                     out + z * (long)SEQ * DIM,
                     DIM, SEQ, 1.0f);
}

// ============================================================
// Launch
// ============================================================
extern "C" void kernel_launch(void* const* d_in, const int* in_sizes, int n_in,
                              void* d_out, int out_size)
{
    const float* x  = (const float*)d_in[0];
    const float* Wq = (const float*)d_in[1];
    const float* Wk = (const float*)d_in[2];
    const float* Wv = (const float*)d_in[3];
    float* out = (float*)d_out;

    // idempotent host-side attribute sets (not stream ops; capture-safe)
    cudaFuncSetAttribute(qkv_kernel,    cudaFuncAttributeMaxDynamicSharedMemorySize, SMEM_NT);
    cudaFuncSetAttribute(scores_kernel, cudaFuncAttributeMaxDynamicSharedMemorySize, SMEM_NT);
    cudaFuncSetAttribute(out_kernel,    cudaFuncAttributeMaxDynamicSharedMemorySize, SMEM_NN);

    dim3 blk(NT);

    dim3 g_qkv(DIM / BN, BT / BM, 3);        // (4, 64, 3)
    qkv_kernel<<<g_qkv, blk, SMEM_NT>>>(x, Wq, Wk, Wv);

    dim3 g_sc(SEQ / BN, SEQ / BM, BATCH);    // (8, 16, 4)
    scores_kernel<<<g_sc, blk, SMEM_NT>>>();

    softmax_kernel<<<BT, blk>>>();           // 8192 rows

    dim3 g_out(DIM / BN, SEQ / BM, BATCH);   // (4, 16, 4)
    out_kernel<<<g_out, blk, SMEM_NN>>>(out);
}